// round 12
// baseline (speedup 1.0000x reference)
#include <cuda_runtime.h>

// ---------------------------------------------------------------------------
// ChordProgressionLoss v12 — R9 math at 64 warps/SM with NO spills.
// Bench evidence: 64w/SM+spills=14.2 (R7), 48w clean=14.2 (R9), 32w clean=17.7
// (R8) -> warp count fills stall slots; spills cost ~nothing but regs cap at
// 32 for 2048thr/SM. Fix: single 29-row chunk per loop iteration -> peak live
// state ~30 regs -> clean codegen at 1024x2. Grid stays 296 (atomic epilogue
// cost unchanged). Math identical: f32x2 magic masks, PRMT jaccard bytes,
// 3 shuffles + dp4a windows, integer max, fixed-point sim. Exact.
// ---------------------------------------------------------------------------

#define NBLK 296
#define THREADS 1024
#define WPB 32

__device__ unsigned long long g_simSlots[32];
__device__ unsigned long long g_penSlots[32];
__device__ unsigned int       g_count = 0;

#define MAGIC2  0x4B4000004B400000ULL
#define INV12_2 0x3DAAAAAB3DAAAAABULL
#define BIAS2   0xBEEAAAABBEEAAAABULL

__device__ __forceinline__ unsigned pcmask(float4 v) {
    unsigned long long dxy, dzw, b1xy, b1zw, t, b2xy, b2zw;
    asm("mov.b64 %0, {%1,%2};" : "=l"(dxy) : "f"(v.x), "f"(v.y));
    asm("mov.b64 %0, {%1,%2};" : "=l"(dzw) : "f"(v.z), "f"(v.w));
    asm("add.rn.f32x2 %0, %1, %2;" : "=l"(b1xy) : "l"(dxy), "l"(MAGIC2));
    asm("add.rn.f32x2 %0, %1, %2;" : "=l"(b1zw) : "l"(dzw), "l"(MAGIC2));
    asm("fma.rn.f32x2 %0, %1, %2, %3;" : "=l"(t) : "l"(dxy), "l"(INV12_2), "l"(BIAS2));
    asm("add.rn.f32x2 %0, %1, %2;" : "=l"(b2xy) : "l"(t), "l"(MAGIC2));
    asm("fma.rn.f32x2 %0, %1, %2, %3;" : "=l"(t) : "l"(dzw), "l"(INV12_2), "l"(BIAS2));
    asm("add.rn.f32x2 %0, %1, %2;" : "=l"(b2zw) : "l"(t), "l"(MAGIC2));
    unsigned a0, a1, a2, a3, q0, q1, q2, q3;
    asm("mov.b64 {%0,%1}, %2;" : "=r"(a0), "=r"(a1) : "l"(b1xy));
    asm("mov.b64 {%0,%1}, %2;" : "=r"(a2), "=r"(a3) : "l"(b1zw));
    asm("mov.b64 {%0,%1}, %2;" : "=r"(q0), "=r"(q1) : "l"(b2xy));
    asm("mov.b64 {%0,%1}, %2;" : "=r"(q2), "=r"(q3) : "l"(b2zw));
    return (1u << ((a0 - 12u * q0) & 31u))
         | (1u << ((a1 - 12u * q1) & 31u))
         | (1u << ((a2 - 12u * q2) & 31u))
         | (1u << ((a3 - 12u * q3) & 31u));
}

__global__ __launch_bounds__(THREADS, 2) void chord_fused(
    const float4* __restrict__ pred, const float4* __restrict__ targ,
    float* __restrict__ out, int T, int nChunks)
{
    __shared__ unsigned sT60[5];
    __shared__ uint2    sSim[21];
    __shared__ unsigned long long redS[WPB], redP[WPB];
    __shared__ bool     sLast;

    const int tid = threadIdx.x;
    if (tid < 5) {
        int p = tid; unsigned w = 0;
        for (int i = 0; i < 4; i++) {
            int dnm = p + 3 - i;
            unsigned t = (dnm > 0) ? (unsigned)((60 * i) / dnm) : 0u;
            w |= (t & 0xFFu) << (8 * i);
        }
        sT60[p] = w;
    }
    if (tid < 16) {
        int p = (tid >> 2) + 1, q = (tid & 3) + 1;
        double r = 1.0 / (((double)p + 12e-6) * ((double)q + 12e-6));
        unsigned R30 = (unsigned)__double2ll_rn(r * 1073741824.0);
        unsigned A30 = (unsigned)__double2ll_rn((1e-6 * (p + q) + 1.2e-11) * r * 1073741824.0);
        sSim[p * 4 + q] = make_uint2(R30, A30);
    }
    __syncthreads();

    const int lane = tid & 31;
    const int wid  = tid >> 5;
    const bool laneOwn = (lane < 29);

    unsigned long long simAcc = 0ull;
    unsigned penAcc = 0u;
    const int rMax = (T > 0) ? (T - 1) : 0;
    const int lastWin = T - 4;

    // grid-stride over single 29-row chunks: minimal live state, no spills
    for (int u = blockIdx.x * WPB + wid; u < nChunks; u += NBLK * WPB) {
        const int r = u * 29 + lane;
        const int c = (r < rMax) ? r : rMax;        // clamped branchless load
        float4 pv = pred[c];
        float4 tv = targ[c];

        unsigned pm = pcmask(pv);
        unsigned tm = pcmask(tv);

        int p  = __popc(pm);                        // 1..4
        int q  = __popc(tm);
        int it = __popc(pm & tm);

        uint2 ra = sSim[p * 4 + q];
        if (laneOwn && (r < T))
            simAcc += (unsigned long long)((unsigned)it * ra.x + ra.y);

        unsigned Tp = sT60[p];
        unsigned iM0 = __popc(pm & 0x091u), iM1 = __popc(pm & 0x221u), iM2 = __popc(pm & 0x884u);
        unsigned im0 = __popc(pm & 0x089u), im1 = __popc(pm & 0x121u), im2 = __popc(pm & 0x484u);
        unsigned selP = iM0 | (im0 << 4) | (iM2 << 8) | (im2 << 12);
        unsigned selQ = iM1 | (im1 << 4);
        unsigned P = __byte_perm(Tp, 0, selP);      // {tM0, tm0, tM2, tm2}
        unsigned Q = __byte_perm(Tp, 0, selQ);      // {tM1, tm1, -, -}

        unsigned Q1 = __shfl_down_sync(0xffffffffu, Q, 1);
        unsigned P2 = __shfl_down_sync(0xffffffffu, P, 2);
        unsigned P3 = __shfl_down_sync(0xffffffffu, P, 3);

        unsigned v1 = __byte_perm(P,  Q1, 0x0040);
        unsigned v2 = __byte_perm(P2, P3, 0x0042);
        unsigned majW = __byte_perm(v1, v2, 0x5410);
        unsigned w1 = __byte_perm(P,  Q1, 0x0051);
        unsigned w2 = __byte_perm(P2, P3, 0x0053);
        unsigned minW = __byte_perm(w1, w2, 0x5410);

        unsigned SM = __dp4a(majW, 0x01010101u, 0u);
        unsigned Sm = __dp4a(minW, 0x01010101u, 0u);
        if (laneOwn && (r <= lastWin))
            penAcc += (SM > Sm) ? SM : Sm;          // 240*(1-min(maj,mino))
    }

    // warp reduction (exact integers -> order-independent)
    unsigned long long penW = (unsigned long long)penAcc;
    #pragma unroll
    for (int o = 16; o; o >>= 1) {
        simAcc += __shfl_xor_sync(0xffffffffu, simAcc, o);
        penW   += __shfl_xor_sync(0xffffffffu, penW,   o);
    }
    if (lane == 0) { redS[wid] = simAcc; redP[wid] = penW; }
    __syncthreads();

    if (wid == 0) {
        unsigned long long s = redS[lane];
        unsigned long long p = redP[lane];
        #pragma unroll
        for (int o = 16; o; o >>= 1) {
            s += __shfl_xor_sync(0xffffffffu, s, o);
            p += __shfl_xor_sync(0xffffffffu, p, o);
        }
        if (lane == 0) {
            int slot = blockIdx.x & 31;
            atomicAdd(&g_simSlots[slot], s);
            atomicAdd(&g_penSlots[slot], p);
            __threadfence();
            sLast = (atomicAdd(&g_count, 1u) == gridDim.x - 1);
        }
    }
    __syncthreads();

    if (sLast && wid == 0) {
        __threadfence();
        unsigned long long s = *(volatile unsigned long long*)&g_simSlots[lane];
        unsigned long long p = *(volatile unsigned long long*)&g_penSlots[lane];
        #pragma unroll
        for (int o = 16; o; o >>= 1) {
            s += __shfl_xor_sync(0xffffffffu, s, o);
            p += __shfl_xor_sync(0xffffffffu, p, o);
        }
        if (lane == 0) {
            double simMean = ((double)s * (1.0 / 1073741824.0)) / (double)T;
            long long nWin = (long long)T - 3;
            double pen = (nWin > 0) ? (0.5 - (double)p / (480.0 * (double)nWin)) : 0.0;
            out[0] = (float)((1.0 - simMean) + pen);
        }
        g_simSlots[lane] = 0ull;   // self-reset for graph replay
        g_penSlots[lane] = 0ull;
        if (lane == 0) g_count = 0;
    }
}

extern "C" void kernel_launch(void* const* d_in, const int* in_sizes, int n_in,
                              void* d_out, int out_size)
{
    const float4* pred = (const float4*)d_in[0];
    const float4* targ = (const float4*)d_in[1];
    int T1 = in_sizes[0] / 4;
    int T2 = in_sizes[1] / 4;
    int T = (T1 < T2) ? T1 : T2;

    int nChunks = (T + 28) / 29;
    if (nChunks < 1) nChunks = 1;
    int blocks = (nChunks + WPB - 1) / WPB;
    if (blocks > NBLK) blocks = NBLK;     // 2 blocks on every SM

    chord_fused<<<blocks, THREADS>>>(pred, targ, (float*)d_out, T, nChunks);
}